// round 5
// baseline (speedup 1.0000x reference)
#include <cuda_runtime.h>
#include <cstdint>
#include <cstddef>

// ---------------- problem constants ----------------
#define NN     50000
#define NE     500000
#define DNODE  64
#define DEDGE  8
#define DIN    72      // DNODE + DEDGE
#define HMSG   128
#define DMSG   64
#define HUPD   64
#define DOUT   32
#define HTEN   32

// ---------------- device scratch (no allocation allowed) ----------------
__device__ float g_aggr[(size_t)NN * DMSG];   // scatter-sum of messages
__device__ float g_cnt[NN];                   // message counts per node
__device__ int   g_idx64;                     // edge_index dtype flag

// ---------------- helpers ----------------
__device__ __forceinline__ void red_add_v2(float* addr, float a, float b) {
    asm volatile("red.global.add.v2.f32 [%0], {%1, %2};"
                 :: "l"(addr), "f"(a), "f"(b) : "memory");
}
__device__ __forceinline__ void red_add_f32(float* addr, float v) {
    asm volatile("red.global.add.f32 [%0], %1;"
                 :: "l"(addr), "f"(v) : "memory");
}

// ---------------- init: zero scratch + detect index dtype ----------------
__global__ void init_kernel(const void* __restrict__ ei) {
    size_t tid    = (size_t)blockIdx.x * blockDim.x + threadIdx.x;
    size_t stride = (size_t)gridDim.x * blockDim.x;
    for (size_t i = tid; i < (size_t)NN * DMSG; i += stride) g_aggr[i] = 0.f;
    for (size_t i = tid; i < (size_t)NN; i += stride)        g_cnt[i]  = 0.f;
    if (tid == 0) {
        // int64 indices: every u64 word is a value in [0, NN).
        // int32 indices: u64 word packs two indices -> high half nonzero almost surely.
        const unsigned long long* p = (const unsigned long long*)ei;
        int is64 = 1;
        for (int k = 0; k < 64; k++)
            if (p[k] >= (unsigned long long)NN) { is64 = 0; break; }
        g_idx64 = is64;
    }
}

// ---------------- edge kernel ----------------
// One warp processes EK_B original edges per iteration; both message
// directions are computed together (backward input = -forward input).
// Produces: RED-scatter of messages into g_aggr/g_cnt, and e_out (tension).
#define EK_NW 16
#define EK_B  4

#define OFF_WM1 0
#define OFF_WM2 (OFF_WM1 + DIN*HMSG)          // 9216
#define OFF_WT1 (OFF_WM2 + HMSG*DMSG)         // 17408
#define OFF_BM1 (OFF_WT1 + DMSG*HTEN)         // 19456
#define OFF_BM2 (OFF_BM1 + HMSG)              // 19584
#define OFF_BT1 (OFF_BM2 + DMSG)              // 19648
#define OFF_WT2 (OFF_BT1 + HTEN)              // 19680
#define OFF_BT2 (OFF_WT2 + HTEN)              // 19712
#define OFF_IN  (OFF_BT2 + 4)                 // 19716 (even -> float2 ok)
#define OFF_H   (OFF_IN + EK_NW*EK_B*DIN)     // 24324
#define EK_SMEM_FLOATS (OFF_H + EK_NW*EK_B*2*HMSG)   // 40708 -> 162832 B

__global__ void __launch_bounds__(EK_NW * 32, 1)
edge_kernel(const float* __restrict__ x, const void* __restrict__ ei,
            const float* __restrict__ ea,
            const float* __restrict__ Wm1, const float* __restrict__ bm1,
            const float* __restrict__ Wm2, const float* __restrict__ bm2,
            const float* __restrict__ Wt1, const float* __restrict__ bt1,
            const float* __restrict__ Wt2, const float* __restrict__ bt2,
            float* __restrict__ e_out)
{
    extern __shared__ float sm[];
    // cooperative weight load (once per persistent block)
    for (int i = threadIdx.x; i < DIN*HMSG;  i += blockDim.x) sm[OFF_WM1+i] = Wm1[i];
    for (int i = threadIdx.x; i < HMSG*DMSG; i += blockDim.x) sm[OFF_WM2+i] = Wm2[i];
    for (int i = threadIdx.x; i < DMSG*HTEN; i += blockDim.x) sm[OFF_WT1+i] = Wt1[i];
    for (int i = threadIdx.x; i < HMSG; i += blockDim.x) sm[OFF_BM1+i] = bm1[i];
    for (int i = threadIdx.x; i < DMSG; i += blockDim.x) sm[OFF_BM2+i] = bm2[i];
    for (int i = threadIdx.x; i < HTEN; i += blockDim.x) {
        sm[OFF_BT1+i] = bt1[i];
        sm[OFF_WT2+i] = Wt2[i];
    }
    if (threadIdx.x == 0) sm[OFF_BT2] = bt2[0];
    __syncthreads();

    const int lane = threadIdx.x & 31;
    const int warp = threadIdx.x >> 5;
    float* in_sh = sm + OFF_IN + warp * (EK_B * DIN);
    float* h_sh  = sm + OFF_H  + warp * (EK_B * 2 * HMSG);
    const float bt2v = sm[OFF_BT2];

    const bool idx64 = (g_idx64 != 0);
    const long long* ei64 = (const long long*)ei;
    const int*       ei32 = (const int*)ei;

    const int gw     = blockIdx.x * EK_NW + warp;
    const int nwarps = gridDim.x * EK_NW;

    for (int base = gw * EK_B; base < NE; base += nwarps * EK_B) {
        int src[EK_B], tgt[EK_B];
        #pragma unroll
        for (int e = 0; e < EK_B; e++) {
            int id = base + e;
            if (idx64) { src[e] = (int)ei64[id]; tgt[e] = (int)ei64[NE + id]; }
            else       { src[e] = ei32[id];      tgt[e] = ei32[NE + id]; }
        }

        // stage input vector [x_t - x_s, ea] per edge
        #pragma unroll
        for (int e = 0; e < EK_B; e++) {
            const float* xs = x + (size_t)src[e] * DNODE;
            const float* xt = x + (size_t)tgt[e] * DNODE;
            in_sh[e*DIN + lane]      = xt[lane]      - xs[lane];
            in_sh[e*DIN + 32 + lane] = xt[32 + lane] - xs[32 + lane];
        }
        if (lane < DEDGE) {
            #pragma unroll
            for (int e = 0; e < EK_B; e++)
                in_sh[e*DIN + DNODE + lane] = ea[(size_t)(base + e) * DEDGE + lane];
        }
        __syncwarp();

        // ---- layer 1: [72] -> [128], both directions share weight loads ----
        float a1[EK_B][4], a2[EK_B][4];
        #pragma unroll
        for (int e = 0; e < EK_B; e++)
            #pragma unroll
            for (int k = 0; k < 4; k++) { a1[e][k] = 0.f; a2[e][k] = 0.f; }

        #pragma unroll 3
        for (int i = 0; i < DIN; i += 2) {
            float w0[4], w1[4];
            #pragma unroll
            for (int k = 0; k < 4; k++) {
                w0[k] = sm[OFF_WM1 + i*HMSG       + 32*k + lane];
                w1[k] = sm[OFF_WM1 + (i+1)*HMSG   + 32*k + lane];
            }
            #pragma unroll
            for (int e = 0; e < EK_B; e++) {
                float2 v = *(const float2*)&in_sh[e*DIN + i];
                #pragma unroll
                for (int k = 0; k < 4; k++) {
                    a1[e][k] = fmaf( v.x, w0[k], a1[e][k]);
                    a1[e][k] = fmaf( v.y, w1[k], a1[e][k]);
                    a2[e][k] = fmaf(-v.x, w0[k], a2[e][k]);
                    a2[e][k] = fmaf(-v.y, w1[k], a2[e][k]);
                }
            }
        }
        #pragma unroll
        for (int e = 0; e < EK_B; e++) {
            #pragma unroll
            for (int k = 0; k < 4; k++) {
                int j = 32*k + lane;
                float b = sm[OFF_BM1 + j];
                h_sh[(e*2 + 0)*HMSG + j] = fmaxf(a1[e][k] + b, 0.f);
                h_sh[(e*2 + 1)*HMSG + j] = fmaxf(a2[e][k] + b, 0.f);
            }
        }
        __syncwarp();

        // ---- layer 2: [128] -> [64], lane owns d = 2*lane, 2*lane+1 ----
        float mm[EK_B][2][2];
        #pragma unroll
        for (int e = 0; e < EK_B; e++)
            #pragma unroll
            for (int d = 0; d < 2; d++) { mm[e][d][0] = 0.f; mm[e][d][1] = 0.f; }

        #pragma unroll 4
        for (int j = 0; j < HMSG; j += 2) {
            float2 wA = *(const float2*)&sm[OFF_WM2 + j*DMSG     + 2*lane];
            float2 wB = *(const float2*)&sm[OFF_WM2 + (j+1)*DMSG + 2*lane];
            #pragma unroll
            for (int e = 0; e < EK_B; e++) {
                #pragma unroll
                for (int d = 0; d < 2; d++) {
                    float2 v = *(const float2*)&h_sh[(e*2 + d)*HMSG + j];
                    mm[e][d][0] = fmaf(v.x, wA.x, mm[e][d][0]);
                    mm[e][d][0] = fmaf(v.y, wB.x, mm[e][d][0]);
                    mm[e][d][1] = fmaf(v.x, wA.y, mm[e][d][1]);
                    mm[e][d][1] = fmaf(v.y, wB.y, mm[e][d][1]);
                }
            }
        }

        // bias + relu, scatter-add, and symmetrized message into in_sh
        const float b0 = sm[OFF_BM2 + 2*lane];
        const float b1 = sm[OFF_BM2 + 2*lane + 1];
        #pragma unroll
        for (int e = 0; e < EK_B; e++) {
            float f0 = fmaxf(mm[e][0][0] + b0, 0.f);   // forward msg -> tgt
            float f1 = fmaxf(mm[e][0][1] + b1, 0.f);
            float g0 = fmaxf(mm[e][1][0] + b0, 0.f);   // backward msg -> src
            float g1 = fmaxf(mm[e][1][1] + b1, 0.f);
            red_add_v2(g_aggr + (size_t)tgt[e]*DMSG + 2*lane, f0, f1);
            red_add_v2(g_aggr + (size_t)src[e]*DMSG + 2*lane, g0, g1);
            in_sh[e*DIN + 2*lane]     = f0 + g0;       // m_sym
            in_sh[e*DIN + 2*lane + 1] = f1 + g1;
        }
        if (lane == 0) {
            #pragma unroll
            for (int e = 0; e < EK_B; e++) {
                red_add_f32(g_cnt + tgt[e], 1.f);
                red_add_f32(g_cnt + src[e], 1.f);
            }
        }
        __syncwarp();

        // ---- tension MLP: [64] -> [32] -> scalar ----
        #pragma unroll
        for (int e = 0; e < EK_B; e++) {
            float acc = 0.f;
            #pragma unroll 8
            for (int d = 0; d < DMSG; d += 2) {
                float2 v = *(const float2*)&in_sh[e*DIN + d];
                acc = fmaf(v.x, sm[OFF_WT1 + d*HTEN     + lane], acc);
                acc = fmaf(v.y, sm[OFF_WT1 + (d+1)*HTEN + lane], acc);
            }
            float hT = fmaxf(acc + sm[OFF_BT1 + lane], 0.f);
            float c  = hT * sm[OFF_WT2 + lane];
            #pragma unroll
            for (int off = 16; off > 0; off >>= 1)
                c += __shfl_xor_sync(0xffffffffu, c, off);
            if (lane == 0) e_out[base + e] = c + bt2v;
        }
        __syncwarp();
    }
}

// ---------------- node kernel: mean + update MLP ----------------
#define NK_NW 16
#define NOFF_WU1 0
#define NOFF_WU2 (NOFF_WU1 + (DNODE+DMSG)*HUPD)   // 8192
#define NOFF_BU1 (NOFF_WU2 + HUPD*DOUT)           // 10240
#define NOFF_BU2 (NOFF_BU1 + HUPD)                // 10304
#define NOFF_IN  (NOFF_BU2 + DOUT)                // 10336
#define NOFF_H   (NOFF_IN + NK_NW*(DNODE+DMSG))   // 12384
#define NK_SMEM_FLOATS (NOFF_H + NK_NW*HUPD)      // 13408 -> 53632 B

__global__ void __launch_bounds__(NK_NW * 32, 1)
node_kernel(const float* __restrict__ x,
            const float* __restrict__ Wu1, const float* __restrict__ bu1,
            const float* __restrict__ Wu2, const float* __restrict__ bu2,
            float* __restrict__ x_out)
{
    extern __shared__ float sm[];
    for (int i = threadIdx.x; i < (DNODE+DMSG)*HUPD; i += blockDim.x) sm[NOFF_WU1+i] = Wu1[i];
    for (int i = threadIdx.x; i < HUPD*DOUT;          i += blockDim.x) sm[NOFF_WU2+i] = Wu2[i];
    for (int i = threadIdx.x; i < HUPD; i += blockDim.x) sm[NOFF_BU1+i] = bu1[i];
    for (int i = threadIdx.x; i < DOUT; i += blockDim.x) sm[NOFF_BU2+i] = bu2[i];
    __syncthreads();

    const int lane = threadIdx.x & 31;
    const int warp = threadIdx.x >> 5;
    float* in_sh = sm + NOFF_IN + warp * (DNODE + DMSG);
    float* h_sh  = sm + NOFF_H  + warp * HUPD;
    const int gw     = blockIdx.x * NK_NW + warp;
    const int nwarps = gridDim.x * NK_NW;

    for (int n = gw; n < NN; n += nwarps) {
        float inv = 1.f / fmaxf(g_cnt[n], 1.f);
        in_sh[lane]      = x[(size_t)n*DNODE + lane];
        in_sh[32 + lane] = x[(size_t)n*DNODE + 32 + lane];
        in_sh[64 + lane] = g_aggr[(size_t)n*DMSG + lane] * inv;
        in_sh[96 + lane] = g_aggr[(size_t)n*DMSG + 32 + lane] * inv;
        __syncwarp();

        float a0 = 0.f, a1 = 0.f;
        #pragma unroll 8
        for (int i = 0; i < DNODE + DMSG; i += 2) {
            float2 v = *(const float2*)&in_sh[i];
            a0 = fmaf(v.x, sm[NOFF_WU1 + i*HUPD         + lane], a0);
            a0 = fmaf(v.y, sm[NOFF_WU1 + (i+1)*HUPD     + lane], a0);
            a1 = fmaf(v.x, sm[NOFF_WU1 + i*HUPD    + 32 + lane], a1);
            a1 = fmaf(v.y, sm[NOFF_WU1 + (i+1)*HUPD + 32 + lane], a1);
        }
        h_sh[lane]      = fmaxf(a0 + sm[NOFF_BU1 + lane], 0.f);
        h_sh[32 + lane] = fmaxf(a1 + sm[NOFF_BU1 + 32 + lane], 0.f);
        __syncwarp();

        float o = 0.f;
        #pragma unroll 8
        for (int j = 0; j < HUPD; j += 2) {
            float2 v = *(const float2*)&h_sh[j];
            o = fmaf(v.x, sm[NOFF_WU2 + j*DOUT     + lane], o);
            o = fmaf(v.y, sm[NOFF_WU2 + (j+1)*DOUT + lane], o);
        }
        x_out[(size_t)n*DOUT + lane] = o + sm[NOFF_BU2 + lane];
        __syncwarp();
    }
}

// ---------------- launch ----------------
extern "C" void kernel_launch(void* const* d_in, const int* in_sizes, int n_in,
                              void* d_out, int out_size)
{
    (void)in_sizes; (void)n_in; (void)out_size;
    const float* x   = (const float*)d_in[0];
    const void*  ei  =               d_in[1];   // int64 or int32 (detected on device)
    const float* ea  = (const float*)d_in[2];
    const float* Wm1 = (const float*)d_in[3];
    const float* bm1 = (const float*)d_in[4];
    const float* Wm2 = (const float*)d_in[5];
    const float* bm2 = (const float*)d_in[6];
    const float* Wu1 = (const float*)d_in[7];
    const float* bu1 = (const float*)d_in[8];
    const float* Wu2 = (const float*)d_in[9];
    const float* bu2 = (const float*)d_in[10];
    const float* Wt1 = (const float*)d_in[11];
    const float* bt1 = (const float*)d_in[12];
    const float* Wt2 = (const float*)d_in[13];
    const float* bt2 = (const float*)d_in[14];

    float* x_out = (float*)d_out;                      // [NN, DOUT]
    float* e_out = x_out + (size_t)NN * DOUT;          // [NE]

    int nsm = 148;
    cudaDeviceGetAttribute(&nsm, cudaDevAttrMultiProcessorCount, 0);

    cudaFuncSetAttribute(edge_kernel, cudaFuncAttributeMaxDynamicSharedMemorySize,
                         EK_SMEM_FLOATS * (int)sizeof(float));
    cudaFuncSetAttribute(node_kernel, cudaFuncAttributeMaxDynamicSharedMemorySize,
                         NK_SMEM_FLOATS * (int)sizeof(float));

    init_kernel<<<1024, 256>>>(ei);
    edge_kernel<<<nsm, EK_NW * 32, EK_SMEM_FLOATS * sizeof(float)>>>(
        x, ei, ea, Wm1, bm1, Wm2, bm2, Wt1, bt1, Wt2, bt2, e_out);
    node_kernel<<<nsm, NK_NW * 32, NK_SMEM_FLOATS * sizeof(float)>>>(
        x, Wu1, bu1, Wu2, bu2, x_out);
}

// round 6
// speedup vs baseline: 1.1380x; 1.1380x over previous
#include <cuda_runtime.h>
#include <cstdint>
#include <cstddef>

// ---------------- problem constants ----------------
#define NN     50000
#define NE     500000
#define DNODE  64
#define DEDGE  8
#define DIN    72
#define HMSG   128
#define DMSG   64
#define HUPD   64
#define DOUT   32
#define HTEN   32

typedef unsigned long long ull;

// ---------------- device scratch ----------------
__device__ float g_aggr[(size_t)NN * DMSG];
__device__ float g_cnt[NN];
__device__ int   g_idx64;

// ---------------- packed f32x2 helpers ----------------
__device__ __forceinline__ ull fma2(ull a, ull b, ull c) {
    ull d; asm("fma.rn.f32x2 %0, %1, %2, %3;" : "=l"(d) : "l"(a), "l"(b), "l"(c));
    return d;
}
__device__ __forceinline__ ull dup2(float x) {
    ull d; asm("mov.b64 %0, {%1, %1};" : "=l"(d) : "f"(x)); return d;
}
__device__ __forceinline__ ull pack2(float x, float y) {
    ull d; asm("mov.b64 %0, {%1, %2};" : "=l"(d) : "f"(x), "f"(y)); return d;
}
__device__ __forceinline__ float2 unpack2(ull v) {
    float2 r; asm("mov.b64 {%0, %1}, %2;" : "=f"(r.x), "=f"(r.y) : "l"(v)); return r;
}
__device__ __forceinline__ void red_add_v2(float* addr, float a, float b) {
    asm volatile("red.global.add.v2.f32 [%0], {%1, %2};"
                 :: "l"(addr), "f"(a), "f"(b) : "memory");
}
__device__ __forceinline__ void red_add_f32(float* addr, float v) {
    asm volatile("red.global.add.f32 [%0], %1;"
                 :: "l"(addr), "f"(v) : "memory");
}

// ---------------- init ----------------
__global__ void init_kernel(const void* __restrict__ ei) {
    size_t tid    = (size_t)blockIdx.x * blockDim.x + threadIdx.x;
    size_t stride = (size_t)gridDim.x * blockDim.x;
    for (size_t i = tid; i < (size_t)NN * DMSG; i += stride) g_aggr[i] = 0.f;
    for (size_t i = tid; i < (size_t)NN; i += stride)        g_cnt[i]  = 0.f;
    if (tid == 0) {
        const unsigned long long* p = (const unsigned long long*)ei;
        int is64 = 1;
        for (int k = 0; k < 64; k++)
            if (p[k] >= (unsigned long long)NN) { is64 = 0; break; }
        g_idx64 = is64;
    }
}

// ---------------- edge kernel ----------------
#define EK_NW 16
#define EK_B  4

#define OFF_WM1 0
#define OFF_WM2 (OFF_WM1 + DIN*HMSG)            // 9216
#define OFF_WT1 (OFF_WM2 + HMSG*DMSG)           // 17408
#define OFF_BM1 (OFF_WT1 + DMSG*HTEN)           // 19456
#define OFF_BM2 (OFF_BM1 + HMSG)                // 19584
#define OFF_BT1 (OFF_BM2 + DMSG)                // 19648
#define OFF_WT2 (OFF_BT1 + HTEN)                // 19680
#define OFF_BT2 (OFF_WT2 + HTEN)                // 19712
#define OFF_IN  (OFF_BT2 + 4)                   // 19716 (16B-aligned in bytes)
#define OFF_H   (OFF_IN + EK_NW*EK_B*2*DIN)     // 28932
#define OFF_MS  (OFF_H + EK_NW*EK_B*2*HMSG)     // 45316
#define EK_SMEM_FLOATS (OFF_MS + EK_NW*EK_B*DMSG)  // 49412 -> 197648 B

__global__ void __launch_bounds__(EK_NW * 32, 1)
edge_kernel(const float* __restrict__ x, const void* __restrict__ ei,
            const float* __restrict__ ea,
            const float* __restrict__ Wm1, const float* __restrict__ bm1,
            const float* __restrict__ Wm2, const float* __restrict__ bm2,
            const float* __restrict__ Wt1, const float* __restrict__ bt1,
            const float* __restrict__ Wt2, const float* __restrict__ bt2,
            float* __restrict__ e_out)
{
    extern __shared__ float sm[];
    for (int i = threadIdx.x; i < DIN*HMSG;  i += blockDim.x) sm[OFF_WM1+i] = Wm1[i];
    for (int i = threadIdx.x; i < HMSG*DMSG; i += blockDim.x) sm[OFF_WM2+i] = Wm2[i];
    for (int i = threadIdx.x; i < DMSG*HTEN; i += blockDim.x) sm[OFF_WT1+i] = Wt1[i];
    for (int i = threadIdx.x; i < HMSG; i += blockDim.x) sm[OFF_BM1+i] = bm1[i];
    for (int i = threadIdx.x; i < DMSG; i += blockDim.x) sm[OFF_BM2+i] = bm2[i];
    for (int i = threadIdx.x; i < HTEN; i += blockDim.x) {
        sm[OFF_BT1+i] = bt1[i];
        sm[OFF_WT2+i] = Wt2[i];
    }
    if (threadIdx.x == 0) sm[OFF_BT2] = bt2[0];
    __syncthreads();

    const int lane = threadIdx.x & 31;
    const int warp = threadIdx.x >> 5;
    const int half = lane >> 4;
    const int l16  = lane & 15;

    float* in_w = sm + OFF_IN + warp * (EK_B * 2 * DIN);    // duplicated inputs
    float* h_w  = sm + OFF_H  + warp * (EK_B * 2 * HMSG);   // {fwd,bwd} interleaved
    float* ms_w = sm + OFF_MS + warp * (EK_B * DMSG);       // symmetrized messages

    // loop-invariant per-lane parameters in registers
    const float4 b1p  = *(const float4*)(sm + OFF_BM1 + 4*lane);   // L1 bias, outputs 4L..4L+3
    const float4 b2p  = *(const float4*)(sm + OFF_BM2 + 4*l16);    // L2 bias, outputs 4*l16..
    const float2 bt1p = *(const float2*)(sm + OFF_BT1 + 2*l16);
    const float2 wt2p = *(const float2*)(sm + OFF_WT2 + 2*l16);
    const float  bt2v = sm[OFF_BT2];

    const bool idx64 = (g_idx64 != 0);
    const long long* ei64 = (const long long*)ei;
    const int*       ei32 = (const int*)ei;

    const int gw     = blockIdx.x * EK_NW + warp;
    const int nwarps = gridDim.x * EK_NW;

    for (int base = gw * EK_B; base < NE; base += nwarps * EK_B) {
        int sr[EK_B], tg[EK_B];
        #pragma unroll
        for (int e = 0; e < EK_B; e++) {
            int id = base + e;
            if (idx64) { sr[e] = (int)ei64[id]; tg[e] = (int)ei64[NE + id]; }
            else       { sr[e] = ei32[id];      tg[e] = ei32[NE + id]; }
        }

        // ---- stage duplicated input [v0,v0,v1,v1,...] per edge ----
        #pragma unroll
        for (int e = 0; e < EK_B; e++) {
            const float2 xt = *(const float2*)(x + (size_t)tg[e]*DNODE + 2*lane);
            const float2 xs = *(const float2*)(x + (size_t)sr[e]*DNODE + 2*lane);
            float4 d;
            d.x = xt.x - xs.x; d.y = d.x;
            d.z = xt.y - xs.y; d.w = d.z;
            *(float4*)(in_w + e*(2*DIN) + 4*lane) = d;
        }
        if (lane < 4*EK_B) {
            int e = lane >> 2, l4 = lane & 3;
            float2 ev = *(const float2*)(ea + (size_t)(base + e)*DEDGE + 2*l4);
            float4 d; d.x = ev.x; d.y = ev.x; d.z = ev.y; d.w = ev.y;
            *(float4*)(in_w + e*(2*DIN) + 2*DNODE + 4*l4) = d;
        }
        __syncwarp();

        // ---- layer 1: z = W1^T.in (forward linear part only) ----
        // lane owns outputs 4L..4L+3; fwd = relu(z+b), bwd = relu(b-z)
        ull z[EK_B][2];
        #pragma unroll
        for (int e = 0; e < EK_B; e++) { z[e][0] = 0ULL; z[e][1] = 0ULL; }

        #pragma unroll 8
        for (int i = 0; i < DIN; i++) {
            float4 w4 = *(const float4*)(sm + OFF_WM1 + i*HMSG + 4*lane);
            ull wa = pack2(w4.x, w4.y);
            ull wb = pack2(w4.z, w4.w);
            #pragma unroll
            for (int e = 0; e < EK_B; e++) {
                ull vv = *(const ull*)(in_w + e*(2*DIN) + 2*i);
                z[e][0] = fma2(vv, wa, z[e][0]);
                z[e][1] = fma2(vv, wb, z[e][1]);
            }
        }
        #pragma unroll
        for (int e = 0; e < EK_B; e++) {
            float2 za = unpack2(z[e][0]);
            float2 zb = unpack2(z[e][1]);
            float4 h0, h1;
            h0.x = fmaxf(za.x + b1p.x, 0.f); h0.y = fmaxf(b1p.x - za.x, 0.f);
            h0.z = fmaxf(za.y + b1p.y, 0.f); h0.w = fmaxf(b1p.y - za.y, 0.f);
            h1.x = fmaxf(zb.x + b1p.z, 0.f); h1.y = fmaxf(b1p.z - zb.x, 0.f);
            h1.z = fmaxf(zb.y + b1p.w, 0.f); h1.w = fmaxf(b1p.w - zb.y, 0.f);
            *(float4*)(h_w + e*(2*HMSG) + 8*lane)     = h0;  // j=4L,4L+1 as {f,b}
            *(float4*)(h_w + e*(2*HMSG) + 8*lane + 4) = h1;  // j=4L+2,4L+3
        }
        __syncwarp();

        // ---- layer 2: half-warp per edge; acc = {m_fwd_o, m_bwd_o} ----
        // lanes 0-15: edges 0 & 2; lanes 16-31: edges 1 & 3. Outputs 4*l16..+3.
        ull acc[2][4];
        #pragma unroll
        for (int k = 0; k < 4; k++) { acc[0][k] = 0ULL; acc[1][k] = 0ULL; }

        const float* hA = h_w + half*(2*HMSG);
        const float* hB = h_w + (2 + half)*(2*HMSG);
        #pragma unroll 4
        for (int j = 0; j < HMSG; j++) {
            float4 w4 = *(const float4*)(sm + OFF_WM2 + j*DMSG + 4*l16);
            ull hvA = *(const ull*)(hA + 2*j);
            ull hvB = *(const ull*)(hB + 2*j);
            ull d0 = dup2(w4.x), d1 = dup2(w4.y), d2 = dup2(w4.z), d3 = dup2(w4.w);
            acc[0][0] = fma2(hvA, d0, acc[0][0]);
            acc[0][1] = fma2(hvA, d1, acc[0][1]);
            acc[0][2] = fma2(hvA, d2, acc[0][2]);
            acc[0][3] = fma2(hvA, d3, acc[0][3]);
            acc[1][0] = fma2(hvB, d0, acc[1][0]);
            acc[1][1] = fma2(hvB, d1, acc[1][1]);
            acc[1][2] = fma2(hvB, d2, acc[1][2]);
            acc[1][3] = fma2(hvB, d3, acc[1][3]);
        }

        #pragma unroll
        for (int es = 0; es < 2; es++) {
            const int e = es*2 + half;
            const int t = half ? tg[es*2+1] : tg[es*2];
            const int s = half ? sr[es*2+1] : sr[es*2];
            float2 a0 = unpack2(acc[es][0]);
            float2 a1 = unpack2(acc[es][1]);
            float2 a2 = unpack2(acc[es][2]);
            float2 a3 = unpack2(acc[es][3]);
            float f0 = fmaxf(a0.x + b2p.x, 0.f), g0 = fmaxf(a0.y + b2p.x, 0.f);
            float f1 = fmaxf(a1.x + b2p.y, 0.f), g1 = fmaxf(a1.y + b2p.y, 0.f);
            float f2 = fmaxf(a2.x + b2p.z, 0.f), g2 = fmaxf(a2.y + b2p.z, 0.f);
            float f3 = fmaxf(a3.x + b2p.w, 0.f), g3 = fmaxf(a3.y + b2p.w, 0.f);
            red_add_v2(g_aggr + (size_t)t*DMSG + 4*l16,     f0, f1);
            red_add_v2(g_aggr + (size_t)t*DMSG + 4*l16 + 2, f2, f3);
            red_add_v2(g_aggr + (size_t)s*DMSG + 4*l16,     g0, g1);
            red_add_v2(g_aggr + (size_t)s*DMSG + 4*l16 + 2, g2, g3);
            float4 sv; sv.x = f0+g0; sv.y = f1+g1; sv.z = f2+g2; sv.w = f3+g3;
            *(float4*)(ms_w + e*DMSG + 4*l16) = sv;
        }
        if (lane == 0) {
            #pragma unroll
            for (int e = 0; e < EK_B; e++) {
                red_add_f32(g_cnt + tg[e], 1.f);
                red_add_f32(g_cnt + sr[e], 1.f);
            }
        }
        __syncwarp();

        // ---- tension MLP: half-warp per edge, f32x2 over d-pairs ----
        #pragma unroll
        for (int p = 0; p < 2; p++) {
            const int e = p*2 + half;
            const float* msp = ms_w + e*DMSG;
            ull accP = 0ULL;                 // {out 2*l16, out 2*l16+1}
            #pragma unroll 8
            for (int d = 0; d < DMSG; d++) {
                ull wv  = *(const ull*)(sm + OFF_WT1 + d*HTEN + 2*l16);
                ull svd = dup2(msp[d]);
                accP = fma2(svd, wv, accP);
            }
            float2 ac = unpack2(accP);
            float h0 = fmaxf(ac.x + bt1p.x, 0.f);
            float h1 = fmaxf(ac.y + bt1p.y, 0.f);
            float c  = h0*wt2p.x + h1*wt2p.y;
            #pragma unroll
            for (int off = 8; off > 0; off >>= 1)
                c += __shfl_xor_sync(0xffffffffu, c, off);
            if (l16 == 0) e_out[base + e] = c + bt2v;
        }
        __syncwarp();
    }
}

// ---------------- node kernel ----------------
#define NK_NW 16
#define NOFF_WU1 0
#define NOFF_WU2 (NOFF_WU1 + (DNODE+DMSG)*HUPD)
#define NOFF_BU1 (NOFF_WU2 + HUPD*DOUT)
#define NOFF_BU2 (NOFF_BU1 + HUPD)
#define NOFF_IN  (NOFF_BU2 + DOUT)
#define NOFF_H   (NOFF_IN + NK_NW*(DNODE+DMSG))
#define NK_SMEM_FLOATS (NOFF_H + NK_NW*HUPD)

__global__ void __launch_bounds__(NK_NW * 32, 1)
node_kernel(const float* __restrict__ x,
            const float* __restrict__ Wu1, const float* __restrict__ bu1,
            const float* __restrict__ Wu2, const float* __restrict__ bu2,
            float* __restrict__ x_out)
{
    extern __shared__ float sm[];
    for (int i = threadIdx.x; i < (DNODE+DMSG)*HUPD; i += blockDim.x) sm[NOFF_WU1+i] = Wu1[i];
    for (int i = threadIdx.x; i < HUPD*DOUT;          i += blockDim.x) sm[NOFF_WU2+i] = Wu2[i];
    for (int i = threadIdx.x; i < HUPD; i += blockDim.x) sm[NOFF_BU1+i] = bu1[i];
    for (int i = threadIdx.x; i < DOUT; i += blockDim.x) sm[NOFF_BU2+i] = bu2[i];
    __syncthreads();

    const int lane = threadIdx.x & 31;
    const int warp = threadIdx.x >> 5;
    float* in_sh = sm + NOFF_IN + warp * (DNODE + DMSG);
    float* h_sh  = sm + NOFF_H  + warp * HUPD;
    const int gw     = blockIdx.x * NK_NW + warp;
    const int nwarps = gridDim.x * NK_NW;

    for (int n = gw; n < NN; n += nwarps) {
        float inv = 1.f / fmaxf(g_cnt[n], 1.f);
        in_sh[lane]      = x[(size_t)n*DNODE + lane];
        in_sh[32 + lane] = x[(size_t)n*DNODE + 32 + lane];
        in_sh[64 + lane] = g_aggr[(size_t)n*DMSG + lane] * inv;
        in_sh[96 + lane] = g_aggr[(size_t)n*DMSG + 32 + lane] * inv;
        __syncwarp();

        float a0 = 0.f, a1 = 0.f;
        #pragma unroll 8
        for (int i = 0; i < DNODE + DMSG; i += 2) {
            float2 v = *(const float2*)&in_sh[i];
            a0 = fmaf(v.x, sm[NOFF_WU1 + i*HUPD         + lane], a0);
            a0 = fmaf(v.y, sm[NOFF_WU1 + (i+1)*HUPD     + lane], a0);
            a1 = fmaf(v.x, sm[NOFF_WU1 + i*HUPD    + 32 + lane], a1);
            a1 = fmaf(v.y, sm[NOFF_WU1 + (i+1)*HUPD + 32 + lane], a1);
        }
        h_sh[lane]      = fmaxf(a0 + sm[NOFF_BU1 + lane], 0.f);
        h_sh[32 + lane] = fmaxf(a1 + sm[NOFF_BU1 + 32 + lane], 0.f);
        __syncwarp();

        float o = 0.f;
        #pragma unroll 8
        for (int j = 0; j < HUPD; j += 2) {
            float2 v = *(const float2*)&h_sh[j];
            o = fmaf(v.x, sm[NOFF_WU2 + j*DOUT     + lane], o);
            o = fmaf(v.y, sm[NOFF_WU2 + (j+1)*DOUT + lane], o);
        }
        x_out[(size_t)n*DOUT + lane] = o + sm[NOFF_BU2 + lane];
        __syncwarp();
    }
}

// ---------------- launch ----------------
extern "C" void kernel_launch(void* const* d_in, const int* in_sizes, int n_in,
                              void* d_out, int out_size)
{
    (void)in_sizes; (void)n_in; (void)out_size;
    const float* x   = (const float*)d_in[0];
    const void*  ei  =               d_in[1];
    const float* ea  = (const float*)d_in[2];
    const float* Wm1 = (const float*)d_in[3];
    const float* bm1 = (const float*)d_in[4];
    const float* Wm2 = (const float*)d_in[5];
    const float* bm2 = (const float*)d_in[6];
    const float* Wu1 = (const float*)d_in[7];
    const float* bu1 = (const float*)d_in[8];
    const float* Wu2 = (const float*)d_in[9];
    const float* bu2 = (const float*)d_in[10];
    const float* Wt1 = (const float*)d_in[11];
    const float* bt1 = (const float*)d_in[12];
    const float* Wt2 = (const float*)d_in[13];
    const float* bt2 = (const float*)d_in[14];

    float* x_out = (float*)d_out;
    float* e_out = x_out + (size_t)NN * DOUT;

    int nsm = 148;
    cudaDeviceGetAttribute(&nsm, cudaDevAttrMultiProcessorCount, 0);

    cudaFuncSetAttribute(edge_kernel, cudaFuncAttributeMaxDynamicSharedMemorySize,
                         EK_SMEM_FLOATS * (int)sizeof(float));
    cudaFuncSetAttribute(node_kernel, cudaFuncAttributeMaxDynamicSharedMemorySize,
                         NK_SMEM_FLOATS * (int)sizeof(float));

    init_kernel<<<1024, 256>>>(ei);
    edge_kernel<<<nsm, EK_NW * 32, EK_SMEM_FLOATS * sizeof(float)>>>(
        x, ei, ea, Wm1, bm1, Wm2, bm2, Wt1, bt1, Wt2, bt2, e_out);
    node_kernel<<<nsm, NK_NW * 32, NK_SMEM_FLOATS * sizeof(float)>>>(
        x, Wu1, bu1, Wu2, bu2, x_out);
}

// round 7
// speedup vs baseline: 1.1408x; 1.0024x over previous
#include <cuda_runtime.h>
#include <cstdint>
#include <cstddef>

// ---------------- problem constants ----------------
#define NN     50000
#define NE     500000
#define DNODE  64
#define DEDGE  8
#define DIN    72
#define HMSG   128
#define DMSG   64
#define HUPD   64
#define DOUT   32
#define HTEN   32

typedef unsigned long long ull;

// ---------------- device scratch ----------------
__device__ float g_aggr[(size_t)NN * DMSG];
__device__ float g_cnt[NN];
__device__ int   g_idx64;

// ---------------- packed f32x2 helpers ----------------
__device__ __forceinline__ ull fma2(ull a, ull b, ull c) {
    ull d; asm("fma.rn.f32x2 %0, %1, %2, %3;" : "=l"(d) : "l"(a), "l"(b), "l"(c));
    return d;
}
__device__ __forceinline__ ull dup2(float x) {
    ull d; asm("mov.b64 %0, {%1, %1};" : "=l"(d) : "f"(x)); return d;
}
__device__ __forceinline__ ull pack2(float x, float y) {
    ull d; asm("mov.b64 %0, {%1, %2};" : "=l"(d) : "f"(x), "f"(y)); return d;
}
__device__ __forceinline__ float2 unpack2(ull v) {
    float2 r; asm("mov.b64 {%0, %1}, %2;" : "=f"(r.x), "=f"(r.y) : "l"(v)); return r;
}
__device__ __forceinline__ void red_add_v2(float* addr, float a, float b) {
    asm volatile("red.global.add.v2.f32 [%0], {%1, %2};"
                 :: "l"(addr), "f"(a), "f"(b) : "memory");
}
__device__ __forceinline__ void red_add_f32(float* addr, float v) {
    asm volatile("red.global.add.f32 [%0], %1;"
                 :: "l"(addr), "f"(v) : "memory");
}

// ---------------- init ----------------
__global__ void init_kernel(const void* __restrict__ ei) {
    size_t tid    = (size_t)blockIdx.x * blockDim.x + threadIdx.x;
    size_t stride = (size_t)gridDim.x * blockDim.x;
    for (size_t i = tid; i < (size_t)NN * DMSG; i += stride) g_aggr[i] = 0.f;
    for (size_t i = tid; i < (size_t)NN; i += stride)        g_cnt[i]  = 0.f;
    if (tid == 0) {
        const unsigned long long* p = (const unsigned long long*)ei;
        int is64 = 1;
        for (int k = 0; k < 64; k++)
            if (p[k] >= (unsigned long long)NN) { is64 = 0; break; }
        g_idx64 = is64;
    }
}

// ---------------- edge kernel ----------------
#define EK_NW 16
#define EK_B  4

#define OFF_WM1 0
#define OFF_WM2 (OFF_WM1 + DIN*HMSG)            // 9216
#define OFF_WT1 (OFF_WM2 + HMSG*DMSG)           // 17408
#define OFF_BM1 (OFF_WT1 + DMSG*HTEN)           // 19456
#define OFF_BM2 (OFF_BM1 + HMSG)                // 19584
#define OFF_BT1 (OFF_BM2 + DMSG)                // 19648
#define OFF_WT2 (OFF_BT1 + HTEN)                // 19680
#define OFF_BT2 (OFF_WT2 + HTEN)                // 19712
#define OFF_IN  (OFF_BT2 + 4)                   // 19716 (16B-aligned in bytes)
#define OFF_H   (OFF_IN + EK_NW*EK_B*2*DIN)     // 28932
#define OFF_MS  (OFF_H + EK_NW*EK_B*2*HMSG)     // 45316
#define EK_SMEM_FLOATS (OFF_MS + EK_NW*EK_B*DMSG)  // 49412 -> 197648 B

__global__ void __launch_bounds__(EK_NW * 32, 1)
edge_kernel(const float* __restrict__ x, const void* __restrict__ ei,
            const float* __restrict__ ea,
            const float* __restrict__ Wm1, const float* __restrict__ bm1,
            const float* __restrict__ Wm2, const float* __restrict__ bm2,
            const float* __restrict__ Wt1, const float* __restrict__ bt1,
            const float* __restrict__ Wt2, const float* __restrict__ bt2,
            float* __restrict__ e_out)
{
    extern __shared__ float sm[];
    for (int i = threadIdx.x; i < DIN*HMSG;  i += blockDim.x) sm[OFF_WM1+i] = Wm1[i];
    for (int i = threadIdx.x; i < HMSG*DMSG; i += blockDim.x) sm[OFF_WM2+i] = Wm2[i];
    for (int i = threadIdx.x; i < DMSG*HTEN; i += blockDim.x) sm[OFF_WT1+i] = Wt1[i];
    for (int i = threadIdx.x; i < HMSG; i += blockDim.x) sm[OFF_BM1+i] = bm1[i];
    for (int i = threadIdx.x; i < DMSG; i += blockDim.x) sm[OFF_BM2+i] = bm2[i];
    for (int i = threadIdx.x; i < HTEN; i += blockDim.x) {
        sm[OFF_BT1+i] = bt1[i];
        sm[OFF_WT2+i] = Wt2[i];
    }
    if (threadIdx.x == 0) sm[OFF_BT2] = bt2[0];
    __syncthreads();

    const int lane = threadIdx.x & 31;
    const int warp = threadIdx.x >> 5;
    const int half = lane >> 4;
    const int l16  = lane & 15;

    float* in_w = sm + OFF_IN + warp * (EK_B * 2 * DIN);    // duplicated inputs
    float* h_w  = sm + OFF_H  + warp * (EK_B * 2 * HMSG);   // {fwd,bwd} interleaved
    float* ms_w = sm + OFF_MS + warp * (EK_B * DMSG);       // symmetrized messages

    // loop-invariant per-lane parameters in registers
    const float4 b1p  = *(const float4*)(sm + OFF_BM1 + 4*lane);   // L1 bias, outputs 4L..4L+3
    const float4 b2p  = *(const float4*)(sm + OFF_BM2 + 4*l16);    // L2 bias, outputs 4*l16..
    const float2 bt1p = *(const float2*)(sm + OFF_BT1 + 2*l16);
    const float2 wt2p = *(const float2*)(sm + OFF_WT2 + 2*l16);
    const float  bt2v = sm[OFF_BT2];

    const bool idx64 = (g_idx64 != 0);
    const long long* ei64 = (const long long*)ei;
    const int*       ei32 = (const int*)ei;

    const int gw     = blockIdx.x * EK_NW + warp;
    const int nwarps = gridDim.x * EK_NW;

    for (int base = gw * EK_B; base < NE; base += nwarps * EK_B) {
        int sr[EK_B], tg[EK_B];
        #pragma unroll
        for (int e = 0; e < EK_B; e++) {
            int id = base + e;
            if (idx64) { sr[e] = (int)ei64[id]; tg[e] = (int)ei64[NE + id]; }
            else       { sr[e] = ei32[id];      tg[e] = ei32[NE + id]; }
        }

        // ---- stage duplicated input [v0,v0,v1,v1,...] per edge ----
        #pragma unroll
        for (int e = 0; e < EK_B; e++) {
            const float2 xt = *(const float2*)(x + (size_t)tg[e]*DNODE + 2*lane);
            const float2 xs = *(const float2*)(x + (size_t)sr[e]*DNODE + 2*lane);
            float4 d;
            d.x = xt.x - xs.x; d.y = d.x;
            d.z = xt.y - xs.y; d.w = d.z;
            *(float4*)(in_w + e*(2*DIN) + 4*lane) = d;
        }
        if (lane < 4*EK_B) {
            int e = lane >> 2, l4 = lane & 3;
            float2 ev = *(const float2*)(ea + (size_t)(base + e)*DEDGE + 2*l4);
            float4 d; d.x = ev.x; d.y = ev.x; d.z = ev.y; d.w = ev.y;
            *(float4*)(in_w + e*(2*DIN) + 2*DNODE + 4*l4) = d;
        }
        __syncwarp();

        // ---- layer 1: z = W1^T.in (forward linear part only) ----
        // lane owns outputs 4L..4L+3; fwd = relu(z+b), bwd = relu(b-z)
        ull z[EK_B][2];
        #pragma unroll
        for (int e = 0; e < EK_B; e++) { z[e][0] = 0ULL; z[e][1] = 0ULL; }

        #pragma unroll 8
        for (int i = 0; i < DIN; i++) {
            float4 w4 = *(const float4*)(sm + OFF_WM1 + i*HMSG + 4*lane);
            ull wa = pack2(w4.x, w4.y);
            ull wb = pack2(w4.z, w4.w);
            #pragma unroll
            for (int e = 0; e < EK_B; e++) {
                ull vv = *(const ull*)(in_w + e*(2*DIN) + 2*i);
                z[e][0] = fma2(vv, wa, z[e][0]);
                z[e][1] = fma2(vv, wb, z[e][1]);
            }
        }
        #pragma unroll
        for (int e = 0; e < EK_B; e++) {
            float2 za = unpack2(z[e][0]);
            float2 zb = unpack2(z[e][1]);
            float4 h0, h1;
            h0.x = fmaxf(za.x + b1p.x, 0.f); h0.y = fmaxf(b1p.x - za.x, 0.f);
            h0.z = fmaxf(za.y + b1p.y, 0.f); h0.w = fmaxf(b1p.y - za.y, 0.f);
            h1.x = fmaxf(zb.x + b1p.z, 0.f); h1.y = fmaxf(b1p.z - zb.x, 0.f);
            h1.z = fmaxf(zb.y + b1p.w, 0.f); h1.w = fmaxf(b1p.w - zb.y, 0.f);
            *(float4*)(h_w + e*(2*HMSG) + 8*lane)     = h0;  // j=4L,4L+1 as {f,b}
            *(float4*)(h_w + e*(2*HMSG) + 8*lane + 4) = h1;  // j=4L+2,4L+3
        }
        __syncwarp();

        // ---- layer 2: half-warp per edge; acc = {m_fwd_o, m_bwd_o} ----
        // lanes 0-15: edges 0 & 2; lanes 16-31: edges 1 & 3. Outputs 4*l16..+3.
        ull acc[2][4];
        #pragma unroll
        for (int k = 0; k < 4; k++) { acc[0][k] = 0ULL; acc[1][k] = 0ULL; }

        const float* hA = h_w + half*(2*HMSG);
        const float* hB = h_w + (2 + half)*(2*HMSG);
        #pragma unroll 4
        for (int j = 0; j < HMSG; j++) {
            float4 w4 = *(const float4*)(sm + OFF_WM2 + j*DMSG + 4*l16);
            ull hvA = *(const ull*)(hA + 2*j);
            ull hvB = *(const ull*)(hB + 2*j);
            ull d0 = dup2(w4.x), d1 = dup2(w4.y), d2 = dup2(w4.z), d3 = dup2(w4.w);
            acc[0][0] = fma2(hvA, d0, acc[0][0]);
            acc[0][1] = fma2(hvA, d1, acc[0][1]);
            acc[0][2] = fma2(hvA, d2, acc[0][2]);
            acc[0][3] = fma2(hvA, d3, acc[0][3]);
            acc[1][0] = fma2(hvB, d0, acc[1][0]);
            acc[1][1] = fma2(hvB, d1, acc[1][1]);
            acc[1][2] = fma2(hvB, d2, acc[1][2]);
            acc[1][3] = fma2(hvB, d3, acc[1][3]);
        }

        #pragma unroll
        for (int es = 0; es < 2; es++) {
            const int e = es*2 + half;
            const int t = half ? tg[es*2+1] : tg[es*2];
            const int s = half ? sr[es*2+1] : sr[es*2];
            float2 a0 = unpack2(acc[es][0]);
            float2 a1 = unpack2(acc[es][1]);
            float2 a2 = unpack2(acc[es][2]);
            float2 a3 = unpack2(acc[es][3]);
            float f0 = fmaxf(a0.x + b2p.x, 0.f), g0 = fmaxf(a0.y + b2p.x, 0.f);
            float f1 = fmaxf(a1.x + b2p.y, 0.f), g1 = fmaxf(a1.y + b2p.y, 0.f);
            float f2 = fmaxf(a2.x + b2p.z, 0.f), g2 = fmaxf(a2.y + b2p.z, 0.f);
            float f3 = fmaxf(a3.x + b2p.w, 0.f), g3 = fmaxf(a3.y + b2p.w, 0.f);
            red_add_v2(g_aggr + (size_t)t*DMSG + 4*l16,     f0, f1);
            red_add_v2(g_aggr + (size_t)t*DMSG + 4*l16 + 2, f2, f3);
            red_add_v2(g_aggr + (size_t)s*DMSG + 4*l16,     g0, g1);
            red_add_v2(g_aggr + (size_t)s*DMSG + 4*l16 + 2, g2, g3);
            float4 sv; sv.x = f0+g0; sv.y = f1+g1; sv.z = f2+g2; sv.w = f3+g3;
            *(float4*)(ms_w + e*DMSG + 4*l16) = sv;
        }
        if (lane == 0) {
            #pragma unroll
            for (int e = 0; e < EK_B; e++) {
                red_add_f32(g_cnt + tg[e], 1.f);
                red_add_f32(g_cnt + sr[e], 1.f);
            }
        }
        __syncwarp();

        // ---- tension MLP: half-warp per edge, f32x2 over d-pairs ----
        #pragma unroll
        for (int p = 0; p < 2; p++) {
            const int e = p*2 + half;
            const float* msp = ms_w + e*DMSG;
            ull accP = 0ULL;                 // {out 2*l16, out 2*l16+1}
            #pragma unroll 8
            for (int d = 0; d < DMSG; d++) {
                ull wv  = *(const ull*)(sm + OFF_WT1 + d*HTEN + 2*l16);
                ull svd = dup2(msp[d]);
                accP = fma2(svd, wv, accP);
            }
            float2 ac = unpack2(accP);
            float h0 = fmaxf(ac.x + bt1p.x, 0.f);
            float h1 = fmaxf(ac.y + bt1p.y, 0.f);
            float c  = h0*wt2p.x + h1*wt2p.y;
            #pragma unroll
            for (int off = 8; off > 0; off >>= 1)
                c += __shfl_xor_sync(0xffffffffu, c, off);
            if (l16 == 0) e_out[base + e] = c + bt2v;
        }
        __syncwarp();
    }
}

// ---------------- node kernel ----------------
#define NK_NW 16
#define NOFF_WU1 0
#define NOFF_WU2 (NOFF_WU1 + (DNODE+DMSG)*HUPD)
#define NOFF_BU1 (NOFF_WU2 + HUPD*DOUT)
#define NOFF_BU2 (NOFF_BU1 + HUPD)
#define NOFF_IN  (NOFF_BU2 + DOUT)
#define NOFF_H   (NOFF_IN + NK_NW*(DNODE+DMSG))
#define NK_SMEM_FLOATS (NOFF_H + NK_NW*HUPD)

__global__ void __launch_bounds__(NK_NW * 32, 1)
node_kernel(const float* __restrict__ x,
            const float* __restrict__ Wu1, const float* __restrict__ bu1,
            const float* __restrict__ Wu2, const float* __restrict__ bu2,
            float* __restrict__ x_out)
{
    extern __shared__ float sm[];
    for (int i = threadIdx.x; i < (DNODE+DMSG)*HUPD; i += blockDim.x) sm[NOFF_WU1+i] = Wu1[i];
    for (int i = threadIdx.x; i < HUPD*DOUT;          i += blockDim.x) sm[NOFF_WU2+i] = Wu2[i];
    for (int i = threadIdx.x; i < HUPD; i += blockDim.x) sm[NOFF_BU1+i] = bu1[i];
    for (int i = threadIdx.x; i < DOUT; i += blockDim.x) sm[NOFF_BU2+i] = bu2[i];
    __syncthreads();

    const int lane = threadIdx.x & 31;
    const int warp = threadIdx.x >> 5;
    float* in_sh = sm + NOFF_IN + warp * (DNODE + DMSG);
    float* h_sh  = sm + NOFF_H  + warp * HUPD;
    const int gw     = blockIdx.x * NK_NW + warp;
    const int nwarps = gridDim.x * NK_NW;

    for (int n = gw; n < NN; n += nwarps) {
        float inv = 1.f / fmaxf(g_cnt[n], 1.f);
        in_sh[lane]      = x[(size_t)n*DNODE + lane];
        in_sh[32 + lane] = x[(size_t)n*DNODE + 32 + lane];
        in_sh[64 + lane] = g_aggr[(size_t)n*DMSG + lane] * inv;
        in_sh[96 + lane] = g_aggr[(size_t)n*DMSG + 32 + lane] * inv;
        __syncwarp();

        float a0 = 0.f, a1 = 0.f;
        #pragma unroll 8
        for (int i = 0; i < DNODE + DMSG; i += 2) {
            float2 v = *(const float2*)&in_sh[i];
            a0 = fmaf(v.x, sm[NOFF_WU1 + i*HUPD         + lane], a0);
            a0 = fmaf(v.y, sm[NOFF_WU1 + (i+1)*HUPD     + lane], a0);
            a1 = fmaf(v.x, sm[NOFF_WU1 + i*HUPD    + 32 + lane], a1);
            a1 = fmaf(v.y, sm[NOFF_WU1 + (i+1)*HUPD + 32 + lane], a1);
        }
        h_sh[lane]      = fmaxf(a0 + sm[NOFF_BU1 + lane], 0.f);
        h_sh[32 + lane] = fmaxf(a1 + sm[NOFF_BU1 + 32 + lane], 0.f);
        __syncwarp();

        float o = 0.f;
        #pragma unroll 8
        for (int j = 0; j < HUPD; j += 2) {
            float2 v = *(const float2*)&h_sh[j];
            o = fmaf(v.x, sm[NOFF_WU2 + j*DOUT     + lane], o);
            o = fmaf(v.y, sm[NOFF_WU2 + (j+1)*DOUT + lane], o);
        }
        x_out[(size_t)n*DOUT + lane] = o + sm[NOFF_BU2 + lane];
        __syncwarp();
    }
}

// ---------------- launch ----------------
extern "C" void kernel_launch(void* const* d_in, const int* in_sizes, int n_in,
                              void* d_out, int out_size)
{
    (void)in_sizes; (void)n_in; (void)out_size;
    const float* x   = (const float*)d_in[0];
    const void*  ei  =               d_in[1];
    const float* ea  = (const float*)d_in[2];
    const float* Wm1 = (const float*)d_in[3];
    const float* bm1 = (const float*)d_in[4];
    const float* Wm2 = (const float*)d_in[5];
    const float* bm2 = (const float*)d_in[6];
    const float* Wu1 = (const float*)d_in[7];
    const float* bu1 = (const float*)d_in[8];
    const float* Wu2 = (const float*)d_in[9];
    const float* bu2 = (const float*)d_in[10];
    const float* Wt1 = (const float*)d_in[11];
    const float* bt1 = (const float*)d_in[12];
    const float* Wt2 = (const float*)d_in[13];
    const float* bt2 = (const float*)d_in[14];

    float* x_out = (float*)d_out;
    float* e_out = x_out + (size_t)NN * DOUT;

    int nsm = 148;
    cudaDeviceGetAttribute(&nsm, cudaDevAttrMultiProcessorCount, 0);

    cudaFuncSetAttribute(edge_kernel, cudaFuncAttributeMaxDynamicSharedMemorySize,
                         EK_SMEM_FLOATS * (int)sizeof(float));
    cudaFuncSetAttribute(node_kernel, cudaFuncAttributeMaxDynamicSharedMemorySize,
                         NK_SMEM_FLOATS * (int)sizeof(float));

    init_kernel<<<1024, 256>>>(ei);
    edge_kernel<<<nsm, EK_NW * 32, EK_SMEM_FLOATS * sizeof(float)>>>(
        x, ei, ea, Wm1, bm1, Wm2, bm2, Wt1, bt1, Wt2, bt2, e_out);
    node_kernel<<<nsm, NK_NW * 32, NK_SMEM_FLOATS * sizeof(float)>>>(
        x, Wu1, bu1, Wu2, bu2, x_out);
}